// round 10
// baseline (speedup 1.0000x reference)
#include <cuda_runtime.h>
#include <cuda_bf16.h>
#include <stdint.h>
#include <math.h>

// Problem constants
#define BATCH 16
#define SEQ 512
#define DM 1024
#define NH 16
#define HD 64
#define NTOK (BATCH * SEQ)   // 8192

// ---------------- scratch (allocation-free: __device__ globals) ----------------
__device__ float g_q[NTOK * DM];
__device__ float g_k[NTOK * DM];
__device__ float g_v[NTOK * DM];
// pre-split weights (Wq,Wk,Wv,Wo) and activations (query,key,value), bf16 hi/lo
__device__ __nv_bfloat16 g_wh[4u * DM * DM];
__device__ __nv_bfloat16 g_wl[4u * DM * DM];
__device__ __nv_bfloat16 g_ah[3u * NTOK * DM];
__device__ __nv_bfloat16 g_al[3u * NTOK * DM];
// attention output, written pre-split
__device__ __nv_bfloat16 g_ctxh[NTOK * DM];
__device__ __nv_bfloat16 g_ctxl[NTOK * DM];

// ---------------- warp-level tensor core primitives (sm_80+, no 'a' target) ----
__device__ __forceinline__ uint32_t smem_u32(const void* p) {
    uint32_t a;
    asm("{ .reg .u64 t; cvta.to.shared.u64 t, %1; cvt.u32.u64 %0, t; }"
        : "=r"(a) : "l"(p));
    return a;
}
__device__ __forceinline__ void ldm_x4(uint32_t* r, uint32_t addr) {
    asm volatile("ldmatrix.sync.aligned.m8n8.x4.shared.b16 {%0,%1,%2,%3}, [%4];"
        : "=r"(r[0]), "=r"(r[1]), "=r"(r[2]), "=r"(r[3]) : "r"(addr));
}
__device__ __forceinline__ void ldm_x2(uint32_t* r, uint32_t addr) {
    asm volatile("ldmatrix.sync.aligned.m8n8.x2.shared.b16 {%0,%1}, [%2];"
        : "=r"(r[0]), "=r"(r[1]) : "r"(addr));
}
__device__ __forceinline__ void ldm_x2t(uint32_t* r, uint32_t addr) {
    asm volatile("ldmatrix.sync.aligned.m8n8.x2.trans.shared.b16 {%0,%1}, [%2];"
        : "=r"(r[0]), "=r"(r[1]) : "r"(addr));
}
__device__ __forceinline__ void mma_bf16(float* d, const uint32_t* a, const uint32_t* b) {
    asm volatile("mma.sync.aligned.m16n8k16.row.col.f32.bf16.bf16.f32 "
        "{%0,%1,%2,%3}, {%4,%5,%6,%7}, {%8,%9}, {%0,%1,%2,%3};"
        : "+f"(d[0]), "+f"(d[1]), "+f"(d[2]), "+f"(d[3])
        : "r"(a[0]), "r"(a[1]), "r"(a[2]), "r"(a[3]), "r"(b[0]), "r"(b[1]));
}
__device__ __forceinline__ void cp16(uint32_t dst, const void* src) {
    asm volatile("cp.async.cg.shared.global [%0], [%1], 16;" :: "r"(dst), "l"(src));
}
#define CP_COMMIT() asm volatile("cp.async.commit_group;" ::: "memory")
template <int N> __device__ __forceinline__ void cp_wait() {
    asm volatile("cp.async.wait_group %0;" :: "n"(N) : "memory");
}

// fast exp on the FMA/ALU pipes (no MUFU). |rel err| < 3e-6 for x <= 0.
__device__ __forceinline__ float fexp(float x) {
    float t = fmaxf(x * 1.4426950408889634f, -125.0f);
    const float magic = 12582912.0f;              // 1.5 * 2^23
    float z = t + magic;
    int   n = __float_as_int(z) - 0x4B400000;
    float f = t - (z - magic);
    float p = 0.00133336f;
    p = fmaf(p, f, 0.00961813f);
    p = fmaf(p, f, 0.05550411f);
    p = fmaf(p, f, 0.24022651f);
    p = fmaf(p, f, 0.69314718f);
    p = fmaf(p, f, 1.0f);
    return p * __int_as_float((n + 127) << 23);
}

// ---------------- pre-split kernels: fp32 -> bf16 hi/lo ------------------------
// hi = truncate-to-bf16(x), lo = truncate-to-bf16(x - hi). Same math everywhere.
__device__ __forceinline__ void split4_store(
    const float* __restrict__ src, __nv_bfloat16* dh, __nv_bfloat16* dl, size_t i)
{
    const float4 v = *reinterpret_cast<const float4*>(src + i);
    const float f[4] = {v.x, v.y, v.z, v.w};
    uint32_t u[4], r[4];
    #pragma unroll
    for (int j = 0; j < 4; j++) {
        u[j] = __float_as_uint(f[j]);
        r[j] = __float_as_uint(f[j] - __uint_as_float(u[j] & 0xFFFF0000u));
    }
    uint2 hi, lo;
    hi.x = __byte_perm(u[0], u[1], 0x7632); hi.y = __byte_perm(u[2], u[3], 0x7632);
    lo.x = __byte_perm(r[0], r[1], 0x7632); lo.y = __byte_perm(r[2], r[3], 0x7632);
    *reinterpret_cast<uint2*>(dh + i) = hi;
    *reinterpret_cast<uint2*>(dl + i) = lo;
}

__global__ __launch_bounds__(256) void split_w_all(
    const float* __restrict__ W0, const float* __restrict__ W1,
    const float* __restrict__ W2, const float* __restrict__ W3)
{
    const float* W = (blockIdx.y == 0) ? W0
                   : (blockIdx.y == 1) ? W1
                   : (blockIdx.y == 2) ? W2 : W3;
    const size_t d0 = (size_t)blockIdx.y * DM * DM;
    const size_t i = ((size_t)blockIdx.x * 256 + threadIdx.x) * 4;
    split4_store(W, g_wh + d0, g_wl + d0, i);
}

__global__ __launch_bounds__(256) void split_act(
    const float* __restrict__ A0, const float* __restrict__ A1,
    const float* __restrict__ A2)
{
    const float* A = (blockIdx.y == 0) ? A0
                   : (blockIdx.y == 1) ? A1 : A2;
    const size_t d0 = (size_t)blockIdx.y * NTOK * DM;
    const size_t i = ((size_t)blockIdx.x * 256 + threadIdx.x) * 4;
    split4_store(A, g_ah + d0, g_al + d0, i);
}

// ================== 2-stage cp.async mma.sync GEMM =============================
// C[m,n] = sum_k A[m,k]*W[n,k] + bias[n]; all operands pre-split bf16.
// CTA 128x128, 256 thr = 8 warps (2m x 4n), warp tile 64x32, BK=32, 2 smem stages.
#define GST 40
#define SSB (128 * GST * 2)   // bytes per array per stage (10240)
// smem: [AH s0|AH s1|AL s0|AL s1|BH s0|BH s1|BL s0|BL s1] = 8*SSB = 81920 B
#define GSMEM (8 * SSB)

// a_sel: 0..2 -> g_ah/g_al tensor, 3 -> g_ctxh/g_ctxl
// dst_sel: 0->g_q, 1->g_k, 2->g_v, 3->Cout
__global__ __launch_bounds__(256) void gemm_mma(
    const float* __restrict__ bias, float* Cout,
    int a_sel, int w_sel, int dst_sel)
{
    const __nv_bfloat16* ah = (a_sel < 3) ? g_ah + (size_t)a_sel * NTOK * DM : g_ctxh;
    const __nv_bfloat16* al = (a_sel < 3) ? g_al + (size_t)a_sel * NTOK * DM : g_ctxl;
    const __nv_bfloat16* wh = g_wh + (size_t)w_sel * DM * DM;
    const __nv_bfloat16* wl = g_wl + (size_t)w_sel * DM * DM;
    float* C = (dst_sel == 0) ? g_q
             : (dst_sel == 1) ? g_k
             : (dst_sel == 2) ? g_v
             : Cout;

    extern __shared__ __align__(16) __nv_bfloat16 smg[];
    const uint32_t smB = smem_u32(smg);

    const int tid = threadIdx.x;
    const int lane = tid & 31;
    const int wid = tid >> 5;
    const int wm = wid & 1;
    const int wn = wid >> 1;
    const int bm = blockIdx.y * 128;
    const int bn = blockIdx.x * 128;

    const int grow = tid >> 1;           // 0..127
    const int gcol = (tid & 1) * 16;     // 0 or 16 (bf16 elems)
    const uint32_t rcB = (uint32_t)(grow * GST + gcol) * 2;   // byte offset in array
    const size_t aRow = (size_t)(bm + grow) * DM + gcol;
    const size_t bRow = (size_t)(bn + grow) * DM + gcol;

    const int la = lane & 15;
    const uint32_t aRowOff = (uint32_t)((wm * 64 + la) * GST + (lane >> 4) * 8) * 2;
    const uint32_t bRowOff = (uint32_t)((wn * 32 + (la & 7)) * GST + ((la >> 3) & 1) * 8) * 2;

    float acc[4][4][4];
    #pragma unroll
    for (int mt = 0; mt < 4; mt++)
        #pragma unroll
        for (int nt = 0; nt < 4; nt++)
            #pragma unroll
            for (int e = 0; e < 4; e++) acc[mt][nt][e] = 0.f;

    // --- prologue: issue stage 0 ---
    {
        const uint32_t d = smB + rcB;
        cp16(d,                ah + aRow); cp16(d + 16,            ah + aRow + 8);
        cp16(d + 2 * SSB,      al + aRow); cp16(d + 2 * SSB + 16,  al + aRow + 8);
        cp16(d + 4 * SSB,      wh + bRow); cp16(d + 4 * SSB + 16,  wh + bRow + 8);
        cp16(d + 6 * SSB,      wl + bRow); cp16(d + 6 * SSB + 16,  wl + bRow + 8);
        CP_COMMIT();
    }

    #pragma unroll 1
    for (int it = 0; it < DM / 32; it++) {
        if (it + 1 < DM / 32) {
            const uint32_t d = smB + ((it + 1) & 1) * SSB + rcB;
            const size_t ao = aRow + (it + 1) * 32;
            const size_t bo = bRow + (it + 1) * 32;
            cp16(d,               ah + ao); cp16(d + 16,           ah + ao + 8);
            cp16(d + 2 * SSB,     al + ao); cp16(d + 2 * SSB + 16, al + ao + 8);
            cp16(d + 4 * SSB,     wh + bo); cp16(d + 4 * SSB + 16, wh + bo + 8);
            cp16(d + 6 * SSB,     wl + bo); cp16(d + 6 * SSB + 16, wl + bo + 8);
            CP_COMMIT();
            cp_wait<1>();
        } else {
            cp_wait<0>();
        }
        __syncthreads();

        const uint32_t sb = (uint32_t)((it & 1) * SSB);
        const uint32_t aHiB = smB + sb;
        const uint32_t aLoB = smB + 2 * SSB + sb;
        const uint32_t bHiB = smB + 4 * SSB + sb;
        const uint32_t bLoB = smB + 6 * SSB + sb;

        #pragma unroll
        for (int kk = 0; kk < 2; kk++) {
            const uint32_t kOff = (uint32_t)(kk * 16) * 2;
            uint32_t ahf[4][4], alf[4][4];
            #pragma unroll
            for (int mt = 0; mt < 4; mt++) {
                const uint32_t ro = aRowOff + (uint32_t)(mt * 16 * GST) * 2 + kOff;
                ldm_x4(ahf[mt], aHiB + ro);
                ldm_x4(alf[mt], aLoB + ro);
            }
            #pragma unroll
            for (int nt = 0; nt < 4; nt++) {
                const uint32_t ro = bRowOff + (uint32_t)(nt * 8 * GST) * 2 + kOff;
                uint32_t bh[2], bl[2];
                ldm_x2(bh, bHiB + ro);
                ldm_x2(bl, bLoB + ro);
                #pragma unroll
                for (int mt = 0; mt < 4; mt++) {
                    mma_bf16(acc[mt][nt], ahf[mt], bh);
                    mma_bf16(acc[mt][nt], ahf[mt], bl);
                    mma_bf16(acc[mt][nt], alf[mt], bh);
                }
            }
        }
        __syncthreads();   // mma reads done before this stage is overwritten
    }

    const int er = lane >> 2;
    const int ec = (lane & 3) * 2;
    #pragma unroll
    for (int mt = 0; mt < 4; mt++) {
        #pragma unroll
        for (int nt = 0; nt < 4; nt++) {
            const int col = bn + wn * 32 + nt * 8 + ec;
            const float b0 = bias[col], b1 = bias[col + 1];
            const int r0 = bm + wm * 64 + mt * 16 + er;
            float2 v0, v1;
            v0.x = acc[mt][nt][0] + b0; v0.y = acc[mt][nt][1] + b1;
            v1.x = acc[mt][nt][2] + b0; v1.y = acc[mt][nt][3] + b1;
            *reinterpret_cast<float2*>(&C[(size_t)r0 * DM + col]) = v0;
            *reinterpret_cast<float2*>(&C[(size_t)(r0 + 8) * DM + col]) = v1;
        }
    }
}

// ---------------- RoPE (verified; unchanged) -----------------------------------
__global__ __launch_bounds__(512) void rope_naive()
{
    const int token = blockIdx.x;
    const int pos = token & (SEQ - 1);
    const int h = threadIdx.x >> 5;
    const int i = threadIdx.x & 31;

    const float expo = (float)(2 * i) / 64.0f;
    const float invf = 1.0f / powf(10000.0f, expo);
    const float ang = (float)pos * invf;
    const float c = cosf(ang);
    const float s = sinf(ang);

    const size_t base = (size_t)token * DM + h * HD;
    float a = g_q[base + i], b = g_q[base + i + 32];
    g_q[base + i]      = a * c - b * s;
    g_q[base + i + 32] = b * c + a * s;
    a = g_k[base + i];  b = g_k[base + i + 32];
    g_k[base + i]      = a * c - b * s;
    g_k[base + i + 32] = b * c + a * s;
}

// ================== mma.sync flash attention (verified R8) =====================
// Change this round: epilogue writes ctx pre-split (bf16 hi/lo) -> g_ctxh/g_ctxl.
#define AST 72

__device__ __forceinline__ void split_pack16(const float* f, uint4* hi, uint4* lo) {
    uint32_t uh[16], ul[16];
    #pragma unroll
    for (int j = 0; j < 16; j++) {
        const uint32_t u = __float_as_uint(f[j]);
        uh[j] = u;
        ul[j] = __float_as_uint(f[j] - __uint_as_float(u & 0xFFFF0000u));
    }
    #pragma unroll
    for (int g = 0; g < 2; g++) {
        hi[g].x = __byte_perm(uh[8*g+0], uh[8*g+1], 0x7632);
        hi[g].y = __byte_perm(uh[8*g+2], uh[8*g+3], 0x7632);
        hi[g].z = __byte_perm(uh[8*g+4], uh[8*g+5], 0x7632);
        hi[g].w = __byte_perm(uh[8*g+6], uh[8*g+7], 0x7632);
        lo[g].x = __byte_perm(ul[8*g+0], ul[8*g+1], 0x7632);
        lo[g].y = __byte_perm(ul[8*g+2], ul[8*g+3], 0x7632);
        lo[g].z = __byte_perm(ul[8*g+4], ul[8*g+5], 0x7632);
        lo[g].w = __byte_perm(ul[8*g+6], ul[8*g+7], 0x7632);
    }
}

__device__ __forceinline__ void load_split_64x64(
    const float* __restrict__ src, __nv_bfloat16* dh, __nv_bfloat16* dl,
    int tid, float scale)
{
    const int row = tid >> 1;
    const int c0 = (tid & 1) * 32;
    const float* p = src + (size_t)row * DM + c0;
    float f[32];
    #pragma unroll
    for (int t = 0; t < 8; t++)
        *reinterpret_cast<float4*>(&f[4 * t]) = reinterpret_cast<const float4*>(p)[t];
    #pragma unroll
    for (int j = 0; j < 32; j++) f[j] *= scale;
    uint4 hi[2], lo[2];
    const int off = row * AST + c0;
    split_pack16(&f[0], hi, lo);
    *reinterpret_cast<uint4*>(&dh[off])     = hi[0];
    *reinterpret_cast<uint4*>(&dh[off + 8]) = hi[1];
    *reinterpret_cast<uint4*>(&dl[off])     = lo[0];
    *reinterpret_cast<uint4*>(&dl[off + 8]) = lo[1];
    split_pack16(&f[16], hi, lo);
    *reinterpret_cast<uint4*>(&dh[off + 16]) = hi[0];
    *reinterpret_cast<uint4*>(&dh[off + 24]) = hi[1];
    *reinterpret_cast<uint4*>(&dl[off + 16]) = lo[0];
    *reinterpret_cast<uint4*>(&dl[off + 24]) = lo[1];
}

__global__ __launch_bounds__(128) void attn_mma()
{
    __shared__ __align__(16) __nv_bfloat16 sKh[64 * AST];
    __shared__ __align__(16) __nv_bfloat16 sKl[64 * AST];
    __shared__ __align__(16) __nv_bfloat16 sVh[64 * AST];
    __shared__ __align__(16) __nv_bfloat16 sVl[64 * AST];

    const int tid = threadIdx.x;
    const int lane = tid & 31;
    const int w = tid >> 5;
    const int q0 = blockIdx.x * 64;
    const int h  = blockIdx.y;
    const int b  = blockIdx.z;
    const size_t base = (size_t)b * SEQ * DM + (size_t)h * HD;

    const uint32_t kHiB = smem_u32(sKh), kLoB = smem_u32(sKl);
    const uint32_t vHiB = smem_u32(sVh), vLoB = smem_u32(sVl);

    load_split_64x64(&g_q[base + (size_t)q0 * DM], sKh, sKl, tid, 0.125f);
    __syncthreads();

    uint32_t qh[4][4], ql[4][4];
    {
        const uint32_t ro0 = (uint32_t)((w * 16 + (lane & 15)) * AST + (lane >> 4) * 8) * 2;
        #pragma unroll
        for (int kc = 0; kc < 4; kc++) {
            ldm_x4(qh[kc], kHiB + ro0 + (uint32_t)(kc * 16) * 2);
            ldm_x4(ql[kc], kLoB + ro0 + (uint32_t)(kc * 16) * 2);
        }
    }
    __syncthreads();

    float o[8][4];
    #pragma unroll
    for (int nt = 0; nt < 8; nt++)
        #pragma unroll
        for (int e = 0; e < 4; e++) o[nt][e] = 0.f;
    float m0 = -3.0e38f, m1 = -3.0e38f, l0 = 0.f, l1 = 0.f;

    const uint32_t bro = (uint32_t)((lane & 7) * AST + ((lane >> 3) & 1) * 8) * 2;
    const uint32_t vro = (uint32_t)(((lane & 7) + 8 * ((lane >> 3) & 1)) * AST) * 2;

    #pragma unroll 1
    for (int kt = 0; kt < SEQ / 64; kt++) {
        load_split_64x64(&g_k[base + (size_t)(kt * 64) * DM], sKh, sKl, tid, 1.0f);
        load_split_64x64(&g_v[base + (size_t)(kt * 64) * DM], sVh, sVl, tid, 1.0f);
        __syncthreads();

        float s[8][4];
        #pragma unroll
        for (int nt = 0; nt < 8; nt++)
            #pragma unroll
            for (int e = 0; e < 4; e++) s[nt][e] = 0.f;

        #pragma unroll
        for (int kc = 0; kc < 4; kc++) {
            const uint32_t kOff = (uint32_t)(kc * 16) * 2;
            #pragma unroll
            for (int nt = 0; nt < 8; nt++) {
                const uint32_t ro = bro + (uint32_t)(nt * 8 * AST) * 2 + kOff;
                uint32_t bh[2], bl[2];
                ldm_x2(bh, kHiB + ro);
                ldm_x2(bl, kLoB + ro);
                mma_bf16(s[nt], qh[kc], bh);
                mma_bf16(s[nt], qh[kc], bl);
                mma_bf16(s[nt], ql[kc], bh);
            }
        }

        float tm0 = -3.0e38f, tm1 = -3.0e38f;
        #pragma unroll
        for (int nt = 0; nt < 8; nt++) {
            tm0 = fmaxf(tm0, fmaxf(s[nt][0], s[nt][1]));
            tm1 = fmaxf(tm1, fmaxf(s[nt][2], s[nt][3]));
        }
        #pragma unroll
        for (int off = 1; off < 4; off <<= 1) {
            tm0 = fmaxf(tm0, __shfl_xor_sync(0xffffffffu, tm0, off));
            tm1 = fmaxf(tm1, __shfl_xor_sync(0xffffffffu, tm1, off));
        }
        const float nm0 = fmaxf(m0, tm0), nm1 = fmaxf(m1, tm1);
        const float corr0 = fexp(m0 - nm0), corr1 = fexp(m1 - nm1);
        float rs0 = 0.f, rs1 = 0.f;
        #pragma unroll
        for (int nt = 0; nt < 8; nt++) {
            s[nt][0] = fexp(s[nt][0] - nm0);
            s[nt][1] = fexp(s[nt][1] - nm0);
            s[nt][2] = fexp(s[nt][2] - nm1);
            s[nt][3] = fexp(s[nt][3] - nm1);
            rs0 += s[nt][0] + s[nt][1];
            rs1 += s[nt][2] + s[nt][3];
        }
        #pragma unroll
        for (int off = 1; off < 4; off <<= 1) {
            rs0 += __shfl_xor_sync(0xffffffffu, rs0, off);
            rs1 += __shfl_xor_sync(0xffffffffu, rs1, off);
        }
        l0 = l0 * corr0 + rs0;  m0 = nm0;
        l1 = l1 * corr1 + rs1;  m1 = nm1;
        #pragma unroll
        for (int nt = 0; nt < 8; nt++) {
            o[nt][0] *= corr0; o[nt][1] *= corr0;
            o[nt][2] *= corr1; o[nt][3] *= corr1;
        }

        uint32_t ph[4][4], pl[4][4];
        #pragma unroll
        for (int j = 0; j < 4; j++) {
            const int ta = 2 * j, tb = 2 * j + 1;
            uint32_t u[8], r[8];
            const float* sv[8] = {&s[ta][0], &s[ta][1], &s[ta][2], &s[ta][3],
                                  &s[tb][0], &s[tb][1], &s[tb][2], &s[tb][3]};
            #pragma unroll
            for (int e = 0; e < 8; e++) {
                const float x = *sv[e];
                u[e] = __float_as_uint(x);
                r[e] = __float_as_uint(x - __uint_as_float(u[e] & 0xFFFF0000u));
            }
            ph[j][0] = __byte_perm(u[0], u[1], 0x7632);
            ph[j][1] = __byte_perm(u[2], u[3], 0x7632);
            ph[j][2] = __byte_perm(u[4], u[5], 0x7632);
            ph[j][3] = __byte_perm(u[6], u[7], 0x7632);
            pl[j][0] = __byte_perm(r[0], r[1], 0x7632);
            pl[j][1] = __byte_perm(r[2], r[3], 0x7632);
            pl[j][2] = __byte_perm(r[4], r[5], 0x7632);
            pl[j][3] = __byte_perm(r[6], r[7], 0x7632);
        }

        #pragma unroll
        for (int j = 0; j < 4; j++) {
            const uint32_t jOff = (uint32_t)(j * 16 * AST) * 2;
            #pragma unroll
            for (int nt = 0; nt < 8; nt++) {
                const uint32_t ro = vro + jOff + (uint32_t)(nt * 8) * 2;
                uint32_t bh[2], bl[2];
                ldm_x2t(bh, vHiB + ro);
                ldm_x2t(bl, vLoB + ro);
                mma_bf16(o[nt], ph[j], bh);
                mma_bf16(o[nt], ph[j], bl);
                mma_bf16(o[nt], pl[j], bh);
            }
        }
        __syncthreads();
    }

    // ---- epilogue: normalize + split ctx to bf16 hi/lo directly ----
    const float i0 = 1.0f / l0, i1 = 1.0f / l1;
    const int er = lane >> 2;
    const int ec = (lane & 3) * 2;
    #pragma unroll
    for (int nt = 0; nt < 8; nt++) {
        const int col = h * HD + nt * 8 + ec;
        const size_t r0 = (size_t)(b * SEQ + q0 + w * 16 + er) * DM + col;
        const size_t r1 = r0 + 8 * DM;
        const float f0 = o[nt][0] * i0, f1 = o[nt][1] * i0;
        const float f2 = o[nt][2] * i1, f3 = o[nt][3] * i1;
        uint32_t u0 = __float_as_uint(f0), u1 = __float_as_uint(f1);
        uint32_t u2 = __float_as_uint(f2), u3 = __float_as_uint(f3);
        uint32_t q0r = __float_as_uint(f0 - __uint_as_float(u0 & 0xFFFF0000u));
        uint32_t q1r = __float_as_uint(f1 - __uint_as_float(u1 & 0xFFFF0000u));
        uint32_t q2r = __float_as_uint(f2 - __uint_as_float(u2 & 0xFFFF0000u));
        uint32_t q3r = __float_as_uint(f3 - __uint_as_float(u3 & 0xFFFF0000u));
        *reinterpret_cast<uint32_t*>(&g_ctxh[r0]) = __byte_perm(u0, u1, 0x7632);
        *reinterpret_cast<uint32_t*>(&g_ctxl[r0]) = __byte_perm(q0r, q1r, 0x7632);
        *reinterpret_cast<uint32_t*>(&g_ctxh[r1]) = __byte_perm(u2, u3, 0x7632);
        *reinterpret_cast<uint32_t*>(&g_ctxl[r1]) = __byte_perm(q2r, q3r, 0x7632);
    }
}

// ---------------- launch -------------------------------------------------------
extern "C" void kernel_launch(void* const* d_in, const int* in_sizes, int n_in,
                              void* d_out, int out_size)
{
    const float* act[3] = {0, 0, 0};
    const float* wgt[4] = {0, 0, 0, 0};
    const float* bia[4] = {0, 0, 0, 0};
    int na = 0, nw = 0, nb = 0;
    for (int i = 0; i < n_in; i++) {
        const int s = in_sizes[i];
        if (s == NTOK * DM)      { if (na < 3) act[na++] = (const float*)d_in[i]; }
        else if (s == DM * DM)   { if (nw < 4) wgt[nw++] = (const float*)d_in[i]; }
        else if (s == DM)        { if (nb < 4) bia[nb++] = (const float*)d_in[i]; }
    }
    const float* query = act[0];
    const float* key   = act[1];
    const float* value = act[2];
    const float* Wq = wgt[0]; const float* Wk = wgt[1];
    const float* Wv = wgt[2]; const float* Wo = wgt[3];
    const float* bq = bia[0]; const float* bk = bia[1];
    const float* bv = bia[2]; const float* bo = bia[3];
    float* out = (float*)d_out;

    // pre-split weights and activations
    split_w_all<<<dim3(DM * DM / 4 / 256, 4), 256>>>(Wq, Wk, Wv, Wo);
    split_act<<<dim3(NTOK * DM / 4 / 256, 3), 256>>>(query, key, value);

    const dim3 ggrid(DM / 128, NTOK / 128);   // (8, 64)
    cudaFuncSetAttribute(gemm_mma, cudaFuncAttributeMaxDynamicSharedMemorySize, GSMEM);

    // QKV projections -> g_q, g_k, g_v
    gemm_mma<<<ggrid, 256, GSMEM>>>(bq, out, 0, 0, 0);
    gemm_mma<<<ggrid, 256, GSMEM>>>(bk, out, 1, 1, 1);
    gemm_mma<<<ggrid, 256, GSMEM>>>(bv, out, 2, 2, 2);

    // RoPE in place on g_q, g_k
    rope_naive<<<NTOK, 512>>>();

    // mma flash attention -> g_ctxh/g_ctxl (pre-split)
    attn_mma<<<dim3(SEQ / 64, NH, BATCH), 128>>>();

    // output projection: ctx @ Wo^T + bo -> out
    gemm_mma<<<ggrid, 256, GSMEM>>>(bo, out, 3, 3, 3);
}

// round 11
// speedup vs baseline: 1.0530x; 1.0530x over previous
#include <cuda_runtime.h>
#include <cuda_bf16.h>
#include <stdint.h>
#include <math.h>

// Problem constants
#define BATCH 16
#define SEQ 512
#define DM 1024
#define NH 16
#define HD 64
#define NTOK (BATCH * SEQ)   // 8192

// ---------------- scratch (allocation-free: __device__ globals) ----------------
__device__ float g_q[NTOK * DM];
__device__ float g_k[NTOK * DM];
__device__ float g_v[NTOK * DM];
__device__ __nv_bfloat16 g_wh[4u * DM * DM];
__device__ __nv_bfloat16 g_wl[4u * DM * DM];
__device__ __nv_bfloat16 g_ah[3u * NTOK * DM];
__device__ __nv_bfloat16 g_al[3u * NTOK * DM];
__device__ __nv_bfloat16 g_ctxh[NTOK * DM];
__device__ __nv_bfloat16 g_ctxl[NTOK * DM];

// ---------------- warp-level tensor core primitives ----------------------------
__device__ __forceinline__ uint32_t smem_u32(const void* p) {
    uint32_t a;
    asm("{ .reg .u64 t; cvta.to.shared.u64 t, %1; cvt.u32.u64 %0, t; }"
        : "=r"(a) : "l"(p));
    return a;
}
__device__ __forceinline__ void ldm_x4(uint32_t* r, uint32_t addr) {
    asm volatile("ldmatrix.sync.aligned.m8n8.x4.shared.b16 {%0,%1,%2,%3}, [%4];"
        : "=r"(r[0]), "=r"(r[1]), "=r"(r[2]), "=r"(r[3]) : "r"(addr));
}
__device__ __forceinline__ void ldm_x2(uint32_t* r, uint32_t addr) {
    asm volatile("ldmatrix.sync.aligned.m8n8.x2.shared.b16 {%0,%1}, [%2];"
        : "=r"(r[0]), "=r"(r[1]) : "r"(addr));
}
__device__ __forceinline__ void ldm_x2t(uint32_t* r, uint32_t addr) {
    asm volatile("ldmatrix.sync.aligned.m8n8.x2.trans.shared.b16 {%0,%1}, [%2];"
        : "=r"(r[0]), "=r"(r[1]) : "r"(addr));
}
__device__ __forceinline__ void mma_bf16(float* d, const uint32_t* a, const uint32_t* b) {
    asm volatile("mma.sync.aligned.m16n8k16.row.col.f32.bf16.bf16.f32 "
        "{%0,%1,%2,%3}, {%4,%5,%6,%7}, {%8,%9}, {%0,%1,%2,%3};"
        : "+f"(d[0]), "+f"(d[1]), "+f"(d[2]), "+f"(d[3])
        : "r"(a[0]), "r"(a[1]), "r"(a[2]), "r"(a[3]), "r"(b[0]), "r"(b[1]));
}
__device__ __forceinline__ void cp16(uint32_t dst, const void* src) {
    asm volatile("cp.async.cg.shared.global [%0], [%1], 16;" :: "r"(dst), "l"(src));
}
#define CP_COMMIT() asm volatile("cp.async.commit_group;" ::: "memory")
template <int N> __device__ __forceinline__ void cp_wait() {
    asm volatile("cp.async.wait_group %0;" :: "n"(N) : "memory");
}

// fast exp on the FMA/ALU pipes (no MUFU). |rel err| < 3e-6 for x <= 0.
__device__ __forceinline__ float fexp(float x) {
    float t = fmaxf(x * 1.4426950408889634f, -125.0f);
    const float magic = 12582912.0f;
    float z = t + magic;
    int   n = __float_as_int(z) - 0x4B400000;
    float f = t - (z - magic);
    float p = 0.00133336f;
    p = fmaf(p, f, 0.00961813f);
    p = fmaf(p, f, 0.05550411f);
    p = fmaf(p, f, 0.24022651f);
    p = fmaf(p, f, 0.69314718f);
    p = fmaf(p, f, 1.0f);
    return p * __int_as_float((n + 127) << 23);
}

// ---------------- pre-split kernels: fp32 -> bf16 hi/lo ------------------------
__device__ __forceinline__ void split4_store(
    const float* __restrict__ src, __nv_bfloat16* dh, __nv_bfloat16* dl, size_t i)
{
    const float4 v = *reinterpret_cast<const float4*>(src + i);
    const float f[4] = {v.x, v.y, v.z, v.w};
    uint32_t u[4], r[4];
    #pragma unroll
    for (int j = 0; j < 4; j++) {
        u[j] = __float_as_uint(f[j]);
        r[j] = __float_as_uint(f[j] - __uint_as_float(u[j] & 0xFFFF0000u));
    }
    uint2 hi, lo;
    hi.x = __byte_perm(u[0], u[1], 0x7632); hi.y = __byte_perm(u[2], u[3], 0x7632);
    lo.x = __byte_perm(r[0], r[1], 0x7632); lo.y = __byte_perm(r[2], r[3], 0x7632);
    *reinterpret_cast<uint2*>(dh + i) = hi;
    *reinterpret_cast<uint2*>(dl + i) = lo;
}

__global__ __launch_bounds__(256) void split_w_all(
    const float* __restrict__ W0, const float* __restrict__ W1,
    const float* __restrict__ W2, const float* __restrict__ W3)
{
    const float* W = (blockIdx.y == 0) ? W0
                   : (blockIdx.y == 1) ? W1
                   : (blockIdx.y == 2) ? W2 : W3;
    const size_t d0 = (size_t)blockIdx.y * DM * DM;
    const size_t i = ((size_t)blockIdx.x * 256 + threadIdx.x) * 4;
    split4_store(W, g_wh + d0, g_wl + d0, i);
}

__global__ __launch_bounds__(256) void split_act(
    const float* __restrict__ A0, const float* __restrict__ A1,
    const float* __restrict__ A2)
{
    const float* A = (blockIdx.y == 0) ? A0
                   : (blockIdx.y == 1) ? A1 : A2;
    const size_t d0 = (size_t)blockIdx.y * NTOK * DM;
    const size_t i = ((size_t)blockIdx.x * 256 + threadIdx.x) * 4;
    split4_store(A, g_ah + d0, g_al + d0, i);
}

// ================== 2-stage cp.async mma.sync GEMM =============================
// Pass-reordered MMA issue: 3 passes of 16 independent MMAs each (no acc chains).
// mode 0: fused QKV (blockIdx.z = sel 0..2); mode 1: O projection (sel 3).
#define GST 40
#define SSB (128 * GST * 2)   // 10240 B per array per stage
#define GSMEM (8 * SSB)       // 81920 B

__global__ __launch_bounds__(256, 2) void gemm_mma(
    const float* __restrict__ b0, const float* __restrict__ b1,
    const float* __restrict__ b2, float* Cout, int mode)
{
    const int sel = (mode == 0) ? (int)blockIdx.z : 3;
    const __nv_bfloat16* ah = (sel < 3) ? g_ah + (size_t)sel * NTOK * DM : g_ctxh;
    const __nv_bfloat16* al = (sel < 3) ? g_al + (size_t)sel * NTOK * DM : g_ctxl;
    const __nv_bfloat16* wh = g_wh + (size_t)sel * DM * DM;
    const __nv_bfloat16* wl = g_wl + (size_t)sel * DM * DM;
    const float* bias = (sel == 0) ? b0 : (sel == 1) ? b1 : (sel == 2) ? b2 : b0;
    float* C = (sel == 0) ? g_q
             : (sel == 1) ? g_k
             : (sel == 2) ? g_v
             : Cout;

    extern __shared__ __align__(16) __nv_bfloat16 smg[];
    const uint32_t smB = smem_u32(smg);

    const int tid = threadIdx.x;
    const int lane = tid & 31;
    const int wid = tid >> 5;
    const int wm = wid & 1;
    const int wn = wid >> 1;
    const int bm = blockIdx.y * 128;
    const int bn = blockIdx.x * 128;

    const int grow = tid >> 1;
    const int gcol = (tid & 1) * 16;
    const uint32_t rcB = (uint32_t)(grow * GST + gcol) * 2;
    const size_t aRow = (size_t)(bm + grow) * DM + gcol;
    const size_t bRow = (size_t)(bn + grow) * DM + gcol;

    const int la = lane & 15;
    const uint32_t aRowOff = (uint32_t)((wm * 64 + la) * GST + (lane >> 4) * 8) * 2;
    const uint32_t bRowOff = (uint32_t)((wn * 32 + (la & 7)) * GST + ((la >> 3) & 1) * 8) * 2;

    float acc[4][4][4];
    #pragma unroll
    for (int mt = 0; mt < 4; mt++)
        #pragma unroll
        for (int nt = 0; nt < 4; nt++)
            #pragma unroll
            for (int e = 0; e < 4; e++) acc[mt][nt][e] = 0.f;

    // prologue: stage 0
    {
        const uint32_t d = smB + rcB;
        cp16(d,               ah + aRow); cp16(d + 16,           ah + aRow + 8);
        cp16(d + 2 * SSB,     al + aRow); cp16(d + 2 * SSB + 16, al + aRow + 8);
        cp16(d + 4 * SSB,     wh + bRow); cp16(d + 4 * SSB + 16, wh + bRow + 8);
        cp16(d + 6 * SSB,     wl + bRow); cp16(d + 6 * SSB + 16, wl + bRow + 8);
        CP_COMMIT();
    }

    #pragma unroll 1
    for (int it = 0; it < DM / 32; it++) {
        if (it + 1 < DM / 32) {
            const uint32_t d = smB + ((it + 1) & 1) * SSB + rcB;
            const size_t ao = aRow + (it + 1) * 32;
            const size_t bo = bRow + (it + 1) * 32;
            cp16(d,               ah + ao); cp16(d + 16,           ah + ao + 8);
            cp16(d + 2 * SSB,     al + ao); cp16(d + 2 * SSB + 16, al + ao + 8);
            cp16(d + 4 * SSB,     wh + bo); cp16(d + 4 * SSB + 16, wh + bo + 8);
            cp16(d + 6 * SSB,     wl + bo); cp16(d + 6 * SSB + 16, wl + bo + 8);
            CP_COMMIT();
            cp_wait<1>();
        } else {
            cp_wait<0>();
        }
        __syncthreads();

        const uint32_t sb = (uint32_t)((it & 1) * SSB);
        const uint32_t aHiB = smB + sb;
        const uint32_t aLoB = smB + 2 * SSB + sb;
        const uint32_t bHiB = smB + 4 * SSB + sb;
        const uint32_t bLoB = smB + 6 * SSB + sb;

        #pragma unroll
        for (int kk = 0; kk < 2; kk++) {
            const uint32_t kOff = (uint32_t)(kk * 16) * 2;
            // load ALL fragments first
            uint32_t ahf[4][4], alf[4][4], bhf[4][2], blf[4][2];
            #pragma unroll
            for (int mt = 0; mt < 4; mt++) {
                const uint32_t ro = aRowOff + (uint32_t)(mt * 16 * GST) * 2 + kOff;
                ldm_x4(ahf[mt], aHiB + ro);
                ldm_x4(alf[mt], aLoB + ro);
            }
            #pragma unroll
            for (int nt = 0; nt < 4; nt++) {
                const uint32_t ro = bRowOff + (uint32_t)(nt * 8 * GST) * 2 + kOff;
                ldm_x2(bhf[nt], bHiB + ro);
                ldm_x2(blf[nt], bLoB + ro);
            }
            // pass 1: hi*hi — 16 independent MMAs
            #pragma unroll
            for (int mt = 0; mt < 4; mt++)
                #pragma unroll
                for (int nt = 0; nt < 4; nt++)
                    mma_bf16(acc[mt][nt], ahf[mt], bhf[nt]);
            // pass 2: hi*lo
            #pragma unroll
            for (int mt = 0; mt < 4; mt++)
                #pragma unroll
                for (int nt = 0; nt < 4; nt++)
                    mma_bf16(acc[mt][nt], ahf[mt], blf[nt]);
            // pass 3: lo*hi
            #pragma unroll
            for (int mt = 0; mt < 4; mt++)
                #pragma unroll
                for (int nt = 0; nt < 4; nt++)
                    mma_bf16(acc[mt][nt], alf[mt], bhf[nt]);
        }
        __syncthreads();
    }

    const int er = lane >> 2;
    const int ec = (lane & 3) * 2;
    #pragma unroll
    for (int mt = 0; mt < 4; mt++) {
        #pragma unroll
        for (int nt = 0; nt < 4; nt++) {
            const int col = bn + wn * 32 + nt * 8 + ec;
            const float c0 = bias[col], c1 = bias[col + 1];
            const int r0 = bm + wm * 64 + mt * 16 + er;
            float2 v0, v1;
            v0.x = acc[mt][nt][0] + c0; v0.y = acc[mt][nt][1] + c1;
            v1.x = acc[mt][nt][2] + c0; v1.y = acc[mt][nt][3] + c1;
            *reinterpret_cast<float2*>(&C[(size_t)r0 * DM + col]) = v0;
            *reinterpret_cast<float2*>(&C[(size_t)(r0 + 8) * DM + col]) = v1;
        }
    }
}

// ---------------- RoPE (verified; unchanged) -----------------------------------
__global__ __launch_bounds__(512) void rope_naive()
{
    const int token = blockIdx.x;
    const int pos = token & (SEQ - 1);
    const int h = threadIdx.x >> 5;
    const int i = threadIdx.x & 31;

    const float expo = (float)(2 * i) / 64.0f;
    const float invf = 1.0f / powf(10000.0f, expo);
    const float ang = (float)pos * invf;
    const float c = cosf(ang);
    const float s = sinf(ang);

    const size_t base = (size_t)token * DM + h * HD;
    float a = g_q[base + i], b = g_q[base + i + 32];
    g_q[base + i]      = a * c - b * s;
    g_q[base + i + 32] = b * c + a * s;
    a = g_k[base + i];  b = g_k[base + i + 32];
    g_k[base + i]      = a * c - b * s;
    g_k[base + i + 32] = b * c + a * s;
}

// ================== mma.sync flash attention (verified R8/R10) =================
#define AST 72

__device__ __forceinline__ void split_pack16(const float* f, uint4* hi, uint4* lo) {
    uint32_t uh[16], ul[16];
    #pragma unroll
    for (int j = 0; j < 16; j++) {
        const uint32_t u = __float_as_uint(f[j]);
        uh[j] = u;
        ul[j] = __float_as_uint(f[j] - __uint_as_float(u & 0xFFFF0000u));
    }
    #pragma unroll
    for (int g = 0; g < 2; g++) {
        hi[g].x = __byte_perm(uh[8*g+0], uh[8*g+1], 0x7632);
        hi[g].y = __byte_perm(uh[8*g+2], uh[8*g+3], 0x7632);
        hi[g].z = __byte_perm(uh[8*g+4], uh[8*g+5], 0x7632);
        hi[g].w = __byte_perm(uh[8*g+6], uh[8*g+7], 0x7632);
        lo[g].x = __byte_perm(ul[8*g+0], ul[8*g+1], 0x7632);
        lo[g].y = __byte_perm(ul[8*g+2], ul[8*g+3], 0x7632);
        lo[g].z = __byte_perm(ul[8*g+4], ul[8*g+5], 0x7632);
        lo[g].w = __byte_perm(ul[8*g+6], ul[8*g+7], 0x7632);
    }
}

__device__ __forceinline__ void load_split_64x64(
    const float* __restrict__ src, __nv_bfloat16* dh, __nv_bfloat16* dl,
    int tid, float scale)
{
    const int row = tid >> 1;
    const int c0 = (tid & 1) * 32;
    const float* p = src + (size_t)row * DM + c0;
    float f[32];
    #pragma unroll
    for (int t = 0; t < 8; t++)
        *reinterpret_cast<float4*>(&f[4 * t]) = reinterpret_cast<const float4*>(p)[t];
    #pragma unroll
    for (int j = 0; j < 32; j++) f[j] *= scale;
    uint4 hi[2], lo[2];
    const int off = row * AST + c0;
    split_pack16(&f[0], hi, lo);
    *reinterpret_cast<uint4*>(&dh[off])     = hi[0];
    *reinterpret_cast<uint4*>(&dh[off + 8]) = hi[1];
    *reinterpret_cast<uint4*>(&dl[off])     = lo[0];
    *reinterpret_cast<uint4*>(&dl[off + 8]) = lo[1];
    split_pack16(&f[16], hi, lo);
    *reinterpret_cast<uint4*>(&dh[off + 16]) = hi[0];
    *reinterpret_cast<uint4*>(&dh[off + 24]) = hi[1];
    *reinterpret_cast<uint4*>(&dl[off + 16]) = lo[0];
    *reinterpret_cast<uint4*>(&dl[off + 24]) = lo[1];
}

__global__ __launch_bounds__(128) void attn_mma()
{
    __shared__ __align__(16) __nv_bfloat16 sKh[64 * AST];
    __shared__ __align__(16) __nv_bfloat16 sKl[64 * AST];
    __shared__ __align__(16) __nv_bfloat16 sVh[64 * AST];
    __shared__ __align__(16) __nv_bfloat16 sVl[64 * AST];

    const int tid = threadIdx.x;
    const int lane = tid & 31;
    const int w = tid >> 5;
    const int q0 = blockIdx.x * 64;
    const int h  = blockIdx.y;
    const int b  = blockIdx.z;
    const size_t base = (size_t)b * SEQ * DM + (size_t)h * HD;

    const uint32_t kHiB = smem_u32(sKh), kLoB = smem_u32(sKl);
    const uint32_t vHiB = smem_u32(sVh), vLoB = smem_u32(sVl);

    load_split_64x64(&g_q[base + (size_t)q0 * DM], sKh, sKl, tid, 0.125f);
    __syncthreads();

    uint32_t qh[4][4], ql[4][4];
    {
        const uint32_t ro0 = (uint32_t)((w * 16 + (lane & 15)) * AST + (lane >> 4) * 8) * 2;
        #pragma unroll
        for (int kc = 0; kc < 4; kc++) {
            ldm_x4(qh[kc], kHiB + ro0 + (uint32_t)(kc * 16) * 2);
            ldm_x4(ql[kc], kLoB + ro0 + (uint32_t)(kc * 16) * 2);
        }
    }
    __syncthreads();

    float o[8][4];
    #pragma unroll
    for (int nt = 0; nt < 8; nt++)
        #pragma unroll
        for (int e = 0; e < 4; e++) o[nt][e] = 0.f;
    float m0 = -3.0e38f, m1 = -3.0e38f, l0 = 0.f, l1 = 0.f;

    const uint32_t bro = (uint32_t)((lane & 7) * AST + ((lane >> 3) & 1) * 8) * 2;
    const uint32_t vro = (uint32_t)(((lane & 7) + 8 * ((lane >> 3) & 1)) * AST) * 2;

    #pragma unroll 1
    for (int kt = 0; kt < SEQ / 64; kt++) {
        load_split_64x64(&g_k[base + (size_t)(kt * 64) * DM], sKh, sKl, tid, 1.0f);
        load_split_64x64(&g_v[base + (size_t)(kt * 64) * DM], sVh, sVl, tid, 1.0f);
        __syncthreads();

        float s[8][4];
        #pragma unroll
        for (int nt = 0; nt < 8; nt++)
            #pragma unroll
            for (int e = 0; e < 4; e++) s[nt][e] = 0.f;

        #pragma unroll
        for (int kc = 0; kc < 4; kc++) {
            const uint32_t kOff = (uint32_t)(kc * 16) * 2;
            #pragma unroll
            for (int nt = 0; nt < 8; nt++) {
                const uint32_t ro = bro + (uint32_t)(nt * 8 * AST) * 2 + kOff;
                uint32_t bh[2], bl[2];
                ldm_x2(bh, kHiB + ro);
                ldm_x2(bl, kLoB + ro);
                mma_bf16(s[nt], qh[kc], bh);
                mma_bf16(s[nt], qh[kc], bl);
                mma_bf16(s[nt], ql[kc], bh);
            }
        }

        float tm0 = -3.0e38f, tm1 = -3.0e38f;
        #pragma unroll
        for (int nt = 0; nt < 8; nt++) {
            tm0 = fmaxf(tm0, fmaxf(s[nt][0], s[nt][1]));
            tm1 = fmaxf(tm1, fmaxf(s[nt][2], s[nt][3]));
        }
        #pragma unroll
        for (int off = 1; off < 4; off <<= 1) {
            tm0 = fmaxf(tm0, __shfl_xor_sync(0xffffffffu, tm0, off));
            tm1 = fmaxf(tm1, __shfl_xor_sync(0xffffffffu, tm1, off));
        }
        const float nm0 = fmaxf(m0, tm0), nm1 = fmaxf(m1, tm1);
        const float corr0 = fexp(m0 - nm0), corr1 = fexp(m1 - nm1);
        float rs0 = 0.f, rs1 = 0.f;
        #pragma unroll
        for (int nt = 0; nt < 8; nt++) {
            s[nt][0] = fexp(s[nt][0] - nm0);
            s[nt][1] = fexp(s[nt][1] - nm0);
            s[nt][2] = fexp(s[nt][2] - nm1);
            s[nt][3] = fexp(s[nt][3] - nm1);
            rs0 += s[nt][0] + s[nt][1];
            rs1 += s[nt][2] + s[nt][3];
        }
        #pragma unroll
        for (int off = 1; off < 4; off <<= 1) {
            rs0 += __shfl_xor_sync(0xffffffffu, rs0, off);
            rs1 += __shfl_xor_sync(0xffffffffu, rs1, off);
        }
        l0 = l0 * corr0 + rs0;  m0 = nm0;
        l1 = l1 * corr1 + rs1;  m1 = nm1;
        #pragma unroll
        for (int nt = 0; nt < 8; nt++) {
            o[nt][0] *= corr0; o[nt][1] *= corr0;
            o[nt][2] *= corr1; o[nt][3] *= corr1;
        }

        uint32_t ph[4][4], pl[4][4];
        #pragma unroll
        for (int j = 0; j < 4; j++) {
            const int ta = 2 * j, tb = 2 * j + 1;
            uint32_t u[8], r[8];
            const float* sv[8] = {&s[ta][0], &s[ta][1], &s[ta][2], &s[ta][3],
                                  &s[tb][0], &s[tb][1], &s[tb][2], &s[tb][3]};
            #pragma unroll
            for (int e = 0; e < 8; e++) {
                const float x = *sv[e];
                u[e] = __float_as_uint(x);
                r[e] = __float_as_uint(x - __uint_as_float(u[e] & 0xFFFF0000u));
            }
            ph[j][0] = __byte_perm(u[0], u[1], 0x7632);
            ph[j][1] = __byte_perm(u[2], u[3], 0x7632);
            ph[j][2] = __byte_perm(u[4], u[5], 0x7632);
            ph[j][3] = __byte_perm(u[6], u[7], 0x7632);
            pl[j][0] = __byte_perm(r[0], r[1], 0x7632);
            pl[j][1] = __byte_perm(r[2], r[3], 0x7632);
            pl[j][2] = __byte_perm(r[4], r[5], 0x7632);
            pl[j][3] = __byte_perm(r[6], r[7], 0x7632);
        }

        #pragma unroll
        for (int j = 0; j < 4; j++) {
            const uint32_t jOff = (uint32_t)(j * 16 * AST) * 2;
            #pragma unroll
            for (int nt = 0; nt < 8; nt++) {
                const uint32_t ro = vro + jOff + (uint32_t)(nt * 8) * 2;
                uint32_t bh[2], bl[2];
                ldm_x2t(bh, vHiB + ro);
                ldm_x2t(bl, vLoB + ro);
                mma_bf16(o[nt], ph[j], bh);
                mma_bf16(o[nt], ph[j], bl);
                mma_bf16(o[nt], pl[j], bh);
            }
        }
        __syncthreads();
    }

    const float i0 = 1.0f / l0, i1 = 1.0f / l1;
    const int er = lane >> 2;
    const int ec = (lane & 3) * 2;
    #pragma unroll
    for (int nt = 0; nt < 8; nt++) {
        const int col = h * HD + nt * 8 + ec;
        const size_t r0 = (size_t)(b * SEQ + q0 + w * 16 + er) * DM + col;
        const size_t r1 = r0 + 8 * DM;
        const float f0 = o[nt][0] * i0, f1 = o[nt][1] * i0;
        const float f2 = o[nt][2] * i1, f3 = o[nt][3] * i1;
        uint32_t u0 = __float_as_uint(f0), u1 = __float_as_uint(f1);
        uint32_t u2 = __float_as_uint(f2), u3 = __float_as_uint(f3);
        uint32_t q0r = __float_as_uint(f0 - __uint_as_float(u0 & 0xFFFF0000u));
        uint32_t q1r = __float_as_uint(f1 - __uint_as_float(u1 & 0xFFFF0000u));
        uint32_t q2r = __float_as_uint(f2 - __uint_as_float(u2 & 0xFFFF0000u));
        uint32_t q3r = __float_as_uint(f3 - __uint_as_float(u3 & 0xFFFF0000u));
        *reinterpret_cast<uint32_t*>(&g_ctxh[r0]) = __byte_perm(u0, u1, 0x7632);
        *reinterpret_cast<uint32_t*>(&g_ctxl[r0]) = __byte_perm(q0r, q1r, 0x7632);
        *reinterpret_cast<uint32_t*>(&g_ctxh[r1]) = __byte_perm(u2, u3, 0x7632);
        *reinterpret_cast<uint32_t*>(&g_ctxl[r1]) = __byte_perm(q2r, q3r, 0x7632);
    }
}

// ---------------- launch -------------------------------------------------------
extern "C" void kernel_launch(void* const* d_in, const int* in_sizes, int n_in,
                              void* d_out, int out_size)
{
    const float* act[3] = {0, 0, 0};
    const float* wgt[4] = {0, 0, 0, 0};
    const float* bia[4] = {0, 0, 0, 0};
    int na = 0, nw = 0, nb = 0;
    for (int i = 0; i < n_in; i++) {
        const int s = in_sizes[i];
        if (s == NTOK * DM)      { if (na < 3) act[na++] = (const float*)d_in[i]; }
        else if (s == DM * DM)   { if (nw < 4) wgt[nw++] = (const float*)d_in[i]; }
        else if (s == DM)        { if (nb < 4) bia[nb++] = (const float*)d_in[i]; }
    }
    const float* query = act[0];
    const float* key   = act[1];
    const float* value = act[2];
    const float* Wq = wgt[0]; const float* Wk = wgt[1];
    const float* Wv = wgt[2]; const float* Wo = wgt[3];
    const float* bq = bia[0]; const float* bk = bia[1];
    const float* bv = bia[2]; const float* bo = bia[3];
    float* out = (float*)d_out;

    // pre-split weights and activations
    split_w_all<<<dim3(DM * DM / 4 / 256, 4), 256>>>(Wq, Wk, Wv, Wo);
    split_act<<<dim3(NTOK * DM / 4 / 256, 3), 256>>>(query, key, value);

    cudaFuncSetAttribute(gemm_mma, cudaFuncAttributeMaxDynamicSharedMemorySize, GSMEM);

    // fused QKV projections (one launch, grid.z selects operand set)
    gemm_mma<<<dim3(DM / 128, NTOK / 128, 3), 256, GSMEM>>>(bq, bk, bv, out, 0);

    // RoPE in place on g_q, g_k
    rope_naive<<<NTOK, 512>>>();

    // mma flash attention -> g_ctxh/g_ctxl (pre-split)
    attn_mma<<<dim3(SEQ / 64, NH, BATCH), 128>>>();

    // output projection: ctx @ Wo^T + bo -> out
    gemm_mma<<<dim3(DM / 128, NTOK / 128, 1), 256, GSMEM>>>(bo, bo, bo, out, 1);
}